// round 7
// baseline (speedup 1.0000x reference)
#include <cuda_runtime.h>
#include <math.h>

// ---------------------------------------------------------------------------
// DifferentiableModalPlate, round 6 — single persistent kernel.
//   u_m(t) = coef_m * exp(-sigma_m (t-1) K) * sin(t * omega_m * K)
//   disp[t] = sum_m u_m(t);  out = disp / (max|disp| + 1e-8)
//
// Phase 1 (synth): thread = 32 consecutive samples x 50 modes. Seed u(t0-1),
// u(t0) via mod-2pi + MUFU sin + MUFU ex2 (coef folded into the exponent,
// coef sign folded into omega), scalar Chebyshev fwd/bwd steps build packed
// seed pairs, then 15 f32x2 steps  U_{k+1} = A2*U_k + B2*U_{k-1}.
// Grid 11 x 128 blocks of 64 threads = 1408 blocks, all resident (10/SM).
// Phase 2: grid-wide counter barrier, then 4 threads per sample sum the 128
// L2-resident partials, shfl-combine, atomicMax peak, barrier, normalize.
// ---------------------------------------------------------------------------

#define TPB     64
#define SPT     32
#define CHUNK   50
#define NCHUNK  128          // CHUNK*NCHUNK == MODES
#define MODES   6400
#define MMAXI   80
#define TROW    22528        // 704*32
#define NGROUP  (TROW / SPT)             // 704
#define XBLK    (NGROUP / TPB)           // 11, exact
#define NBLK    (XBLK * NCHUNK)          // 1408

typedef unsigned long long u64t;

__device__ float    g_part[NCHUNK][TROW];   // 11.5 MB, L2-resident
__device__ unsigned g_peak_bits;
__device__ unsigned g_c1;
__device__ unsigned g_c2;

// ---- packed f32x2 helpers --------------------------------------------------
__device__ __forceinline__ u64t pack2(float lo, float hi) {
    u64t r; asm("mov.b64 %0, {%1, %2};" : "=l"(r) : "f"(lo), "f"(hi)); return r;
}
__device__ __forceinline__ float2 unpack2(u64t v) {
    float2 r; asm("mov.b64 {%0, %1}, %2;" : "=f"(r.x), "=f"(r.y) : "l"(v)); return r;
}
__device__ __forceinline__ u64t mul2(u64t a, u64t b) {
    u64t r; asm("mul.rn.f32x2 %0, %1, %2;" : "=l"(r) : "l"(a), "l"(b)); return r;
}
__device__ __forceinline__ u64t add2(u64t a, u64t b) {
    u64t r; asm("add.rn.f32x2 %0, %1, %2;" : "=l"(r) : "l"(a), "l"(b)); return r;
}
__device__ __forceinline__ u64t fma2(u64t a, u64t b, u64t c) {
    u64t r; asm("fma.rn.f32x2 %0, %1, %2, %3;" : "=l"(r) : "l"(a), "l"(b), "l"(c)); return r;
}
__device__ __forceinline__ float ex2a(float x) {
    float y; asm("ex2.approx.f32 %0, %1;" : "=f"(y) : "f"(x)); return y;
}

__device__ __forceinline__ float softplus_ref(float x) {
    return fmaxf(x, 0.0f) + log1pf(expf(-fabsf(x)));
}
__device__ __forceinline__ float sigmoid_ref(float x) {
    if (x >= 0.0f) { float e = expf(-x); return 1.0f / (1.0f + e); }
    float e = expf(x); return e / (1.0f + e);
}

// ---- per-mode parameter computation ----------------------------------------
// A = {w1s (sign-folded), nsig = -sigK*log2e, lc = log2|coef|, A1}
// B = {A2, B2, B1, invB1}
__device__ void prep_mode(int i,
                          const float* mu_raw, const float* Dmu_raw,
                          const float* T0mu_raw, const float* Ly_raw,
                          const float* xo_raw, const float* yo_raw,
                          float4* outA, float4* outB)
{
    const float K_F   = (float)(1.0 / 44100.0);
    const float KK_F  = (float)((1.0 / 44100.0) * (1.0 / 44100.0));
    const float PI_F  = (float)M_PI;
    const float XIPI  = (float)((0.1 * 0.5) * M_PI);
    const float MAXOM = (float)(10000.0 * 2.0 * M_PI);
    const float MINOM = (float)(20.0 * 2.0 * M_PI);
    const double OM2SQ_D = (2.0 * M_PI * 500.0) * (2.0 * M_PI * 500.0);
    const float ALPHA_F = (float)(3.0 * log(10.0) / OM2SQ_D * (OM2SQ_D / 6.0));
    const float BETA_F  = (float)(3.0 * log(10.0) / OM2SQ_D * (1.0 / 1.0 - 1.0 / 6.0));

    float mu  = __fmul_rn(__fadd_rn(softplus_ref(*mu_raw),   1e-4f), 2.43f);
    float Dm  = __fmul_rn(__fadd_rn(softplus_ref(*Dmu_raw),  1e-4f), 0.002452f);
    float T0m = __fmul_rn(__fadd_rn(softplus_ref(*T0mu_raw), 1e-4f), 0.004115f);
    float Ly  = __fadd_rn(1.1f, __fmul_rn((float)(4.0 - 1.1), sigmoid_ref(*Ly_raw)));
    float xo  = __fadd_rn((float)(0.49 * 0.5),
                          __fmul_rn((float)((1.0 - 0.49) * 0.5), sigmoid_ref(*xo_raw)));
    float yo  = __fadd_rn(__fmul_rn(0.51f, Ly),
                          __fmul_rn(__fmul_rn((float)(1.0 - 0.51), Ly), sigmoid_ref(*yo_raw)));
    float yi  = __fmul_rn(0.1f, Ly);
    float ms  = __fmul_rn(__fmul_rn(__fmul_rn(0.25f, mu), 0.5f), Ly);

    float mf = (float)(i / MMAXI + 1);
    float nf = (float)(i % MMAXI + 1);
    float a = __fdiv_rn(__fmul_rn(mf, PI_F), 0.5f);
    float b = __fdiv_rn(__fmul_rn(nf, PI_F), Ly);
    float g1 = __fadd_rn(__fmul_rn(a, a), __fmul_rn(b, b));
    float osq = __fadd_rn(__fmul_rn(T0m, g1), __fmul_rn(__fmul_rn(Dm, g1), g1));
    float omega = sqrtf(fmaxf(osq, 0.0f));
    float valid = (omega <= MAXOM && omega >= MINOM) ? 1.0f : 0.0f;

    float InW = __fmul_rn(
        cosf(__fdiv_rn(__fmul_rn(XIPI, mf), 0.5f)),
        cosf(__fdiv_rn(__fmul_rn(__fmul_rn(yi, PI_F), nf), Ly)));
    float OutW = __fmul_rn(
        cosf(__fdiv_rn(__fmul_rn(__fmul_rn(xo, PI_F), mf), 0.5f)),
        cosf(__fdiv_rn(__fmul_rn(__fmul_rn(yo, PI_F), nf), Ly)));

    float sigma = __fadd_rn(ALPHA_F, __fmul_rn(BETA_F, __fmul_rn(omega, omega)));
    float e0 = expf(__fmul_rn(-sigma, K_F));
    float P = __fmul_rn(
        __fdiv_rn(__fmul_rn(__fmul_rn(__fmul_rn(OutW, InW), KK_F), e0), ms), valid);

    float w1   = __fmul_rn(omega, K_F);
    float s1   = sinf(w1);
    float c1   = cosf(w1);
    float c2w  = cosf(2.0f * w1);
    float den  = __fadd_rn(s1, 1e-8f);
    float coef = __fdiv_rn(P, den);
    float sigK = __fmul_rn(sigma, K_F);
    float e1   = expf(-sigK);
    float e2   = e1 * e1;

    // fold sign of coef into w1 (sin odd; A1,B1,A2,B2 even in omega)
    float w1s = (coef < 0.0f) ? -w1 : w1;
    float lc  = log2f(fabsf(coef));          // -inf when coef == 0 -> e = 0

    float A1 = 2.0f * e1 * c1;
    float B1 = -e2;
    float invB1 = -1.0f / e2;
    float A2 = 2.0f * e2 * c2w;
    float B2 = -(e2 * e2);

    *outA = make_float4(w1s, -sigK * 1.4426950408889634f, lc, A1);
    *outB = make_float4(A2, B2, B1, invB1);
}

// ---- the single persistent kernel ------------------------------------------
__global__ void __launch_bounds__(TPB, 10)
plate_kernel(const float* mu_raw, const float* Dmu_raw,
             const float* T0mu_raw, const float* Ly_raw,
             const float* xo_raw, const float* yo_raw,
             float* __restrict__ out, int T)
{
    const float TWOOPI = 0.63661977236758134f;
    const float TPI_HI = 6.283185482025146484375f;   // fl32(2*pi)
    const float TPI_LO = -1.7484555e-7f;             // 2*pi - TPI_HI

    __shared__ float4 smA[CHUNK];
    __shared__ float4 smB[CHUNK];

    // reset inter-launch state (blocks cannot reach the barrier for ~20us,
    // so this races with nothing)
    if (blockIdx.x == 0 && blockIdx.y == 0 && threadIdx.x == 0) {
        g_peak_bits = 0u;
        g_c1 = 0u;
        g_c2 = 0u;
        __threadfence();
    }

    int base = blockIdx.y * CHUNK;
    if (threadIdx.x < CHUNK) {
        prep_mode(base + threadIdx.x, mu_raw, Dmu_raw, T0mu_raw,
                  Ly_raw, xo_raw, yo_raw,
                  &smA[threadIdx.x], &smB[threadIdx.x]);
    }
    __syncthreads();

    // ---------------- phase 1: synthesis ----------------
    int g = blockIdx.x * TPB + threadIdx.x;      // 0..703, exact
    int   t0    = g * SPT;
    float t0f   = (float)t0;
    float t0m1f = t0f - 1.0f;
    float t0m2f = t0f - 2.0f;

    u64t acc[SPT / 2];
    #pragma unroll
    for (int k = 0; k < SPT / 2; ++k) acc[k] = 0ull;

    #pragma unroll 1
    for (int j = 0; j < CHUNK; ++j) {
        float4 A = smA[j];
        float4 B = smB[j];

        // seed u(t0) = sgn*|coef| * exp(-sigma*(t0-1)K) * sin(t0*w)
        float ph = t0f * A.x;
        float z  = ph * TWOOPI;
        float q  = rintf(z);
        float r  = fmaf(q, -TPI_HI, ph);
        r        = fmaf(q, -TPI_LO, r);
        float u0 = ex2a(fmaf(t0m1f, A.y, A.z)) * __sinf(r);

        // seed u(t0-1)
        float phm = t0m1f * A.x;
        float zm  = phm * TWOOPI;
        float qm  = rintf(zm);
        float rm  = fmaf(qm, -TPI_HI, phm);
        rm        = fmaf(qm, -TPI_LO, rm);
        float um1 = ex2a(fmaf(t0m2f, A.y, A.z)) * __sinf(rm);

        // scalar Chebyshev forward/backward steps (Delta = 1)
        float u1  = fmaf(A.w, u0, B.z * um1);          // A1*u0 + B1*u(-1)
        float um2 = fmaf(-A.w, um1, u0) * B.w;         // (u0 - A1*u(-1)) * invB1

        u64t A2v   = pack2(B.x, B.x);
        u64t B2v   = pack2(B.y, B.y);
        u64t Ucur  = pack2(u0, u1);
        u64t Uprev = pack2(um2, um1);

        acc[0] = add2(acc[0], Ucur);
        #pragma unroll
        for (int k = 1; k < SPT / 2; ++k) {
            u64t tmp = mul2(B2v, Uprev);
            u64t Un  = fma2(A2v, Ucur, tmp);
            acc[k] = add2(acc[k], Un);
            Uprev = Ucur;
            Ucur  = Un;
        }
    }

    {
        float4* dst = reinterpret_cast<float4*>(&g_part[blockIdx.y][t0]);
        #pragma unroll
        for (int k = 0; k < SPT / 2; k += 2) {
            float2 p  = unpack2(acc[k]);
            float2 qq = unpack2(acc[k + 1]);
            dst[k / 2] = make_float4(p.x, p.y, qq.x, qq.y);
        }
    }

    // ---------------- barrier 1 (all 1408 blocks resident) ----------------
    __threadfence();
    __syncthreads();
    if (threadIdx.x == 0) {
        atomicAdd(&g_c1, 1u);
        while (*((volatile unsigned*)&g_c1) < (unsigned)NBLK) { }
    }
    __syncthreads();
    __threadfence();

    // ---------------- phase 2: combine + peak ----------------
    unsigned lin  = blockIdx.y * XBLK + blockIdx.x;          // 0..1407
    unsigned gtid = lin * TPB + threadIdx.x;                 // 0..90111
    int t   = (int)(gtid >> 2);                              // 0..22527
    int sub = (int)(gtid & 3u);

    float v = 0.0f;
    {
        const float* col = &g_part[sub * 32][t];
        #pragma unroll
        for (int c = 0; c < 32; ++c)
            v += col[(size_t)c * TROW];
    }
    v += __shfl_down_sync(0xffffffffu, v, 2, 4);
    v += __shfl_down_sync(0xffffffffu, v, 1, 4);

    float av = (sub == 0 && t < T) ? fabsf(v) : 0.0f;
    unsigned b = __reduce_max_sync(0xffffffffu, __float_as_uint(av));
    if ((threadIdx.x & 31) == 0) atomicMax(&g_peak_bits, b);

    // ---------------- barrier 2 ----------------
    __syncthreads();
    if (threadIdx.x == 0) {
        __threadfence();
        atomicAdd(&g_c2, 1u);
        while (*((volatile unsigned*)&g_c2) < (unsigned)NBLK) { }
    }
    __syncthreads();

    float peak = __uint_as_float(*((volatile unsigned*)&g_peak_bits));
    if (sub == 0 && t < T)
        out[t] = __fdiv_rn(v, __fadd_rn(peak, 1e-8f));
}

// ---------------------------------------------------------------------------
extern "C" void kernel_launch(void* const* d_in, const int* in_sizes, int n_in,
                              void* d_out, int out_size)
{
    const float* mu_raw   = (const float*)d_in[0];
    const float* Dmu_raw  = (const float*)d_in[1];
    const float* T0mu_raw = (const float*)d_in[2];
    const float* Ly_raw   = (const float*)d_in[3];
    const float* xo_raw   = (const float*)d_in[4];
    const float* yo_raw   = (const float*)d_in[5];
    float* out = (float*)d_out;

    int T = out_size;
    if (T > TROW) T = TROW;

    dim3 grid(XBLK, NCHUNK);
    plate_kernel<<<grid, TPB>>>(mu_raw, Dmu_raw, T0mu_raw,
                                Ly_raw, xo_raw, yo_raw, out, T);
}

// round 9
// speedup vs baseline: 1.0027x; 1.0027x over previous
#include <cuda_runtime.h>
#include <math.h>

// ---------------------------------------------------------------------------
// DifferentiableModalPlate, round 7 — persistent kernel + 2-mode ILP.
//   u_m(t) = coef_m * exp(-sigma_m (t-1) K) * sin(t * omega_m * K)
//   disp[t] = sum_m u_m(t);  out = disp / (max|disp| + 1e-8)
//
// Phase 1: thread = 32 consecutive samples; inner loop processes TWO modes
// per iteration with independent packed Chebyshev chains
//   U_{k+1} = A2*U_k + B2*U_{k-1}   (f32x2, strictly stable)
// doubling the ILP that hides the fma2 dependency latency (R6 profile:
// issue 29% == fma 29.5% -> latency-bound, not throughput-bound).
// Grid 11 x 128 = 1408 blocks x 64 thr, all resident (10/SM); grid-wide
// counter barriers with nanosleep backoff; phase 2 sums 128 L2-resident
// partials at 4 threads/sample, atomicMax peak, normalize.
// ---------------------------------------------------------------------------

#define TPB     64
#define SPT     32
#define CHUNK   50
#define NCHUNK  128          // CHUNK*NCHUNK == MODES
#define MODES   6400
#define MMAXI   80
#define TROW    22528        // 704*32
#define NGROUP  (TROW / SPT)             // 704
#define XBLK    (NGROUP / TPB)           // 11, exact
#define NBLK    (XBLK * NCHUNK)          // 1408

typedef unsigned long long u64t;

__device__ float    g_part[NCHUNK][TROW];   // 11.5 MB, L2-resident
__device__ unsigned g_peak_bits;
__device__ unsigned g_c1;
__device__ unsigned g_c2;

// ---- packed f32x2 helpers --------------------------------------------------
__device__ __forceinline__ u64t pack2(float lo, float hi) {
    u64t r; asm("mov.b64 %0, {%1, %2};" : "=l"(r) : "f"(lo), "f"(hi)); return r;
}
__device__ __forceinline__ float2 unpack2(u64t v) {
    float2 r; asm("mov.b64 {%0, %1}, %2;" : "=f"(r.x), "=f"(r.y) : "l"(v)); return r;
}
__device__ __forceinline__ u64t mul2(u64t a, u64t b) {
    u64t r; asm("mul.rn.f32x2 %0, %1, %2;" : "=l"(r) : "l"(a), "l"(b)); return r;
}
__device__ __forceinline__ u64t add2(u64t a, u64t b) {
    u64t r; asm("add.rn.f32x2 %0, %1, %2;" : "=l"(r) : "l"(a), "l"(b)); return r;
}
__device__ __forceinline__ u64t fma2(u64t a, u64t b, u64t c) {
    u64t r; asm("fma.rn.f32x2 %0, %1, %2, %3;" : "=l"(r) : "l"(a), "l"(b), "l"(c)); return r;
}
__device__ __forceinline__ float ex2a(float x) {
    float y; asm("ex2.approx.f32 %0, %1;" : "=f"(y) : "f"(x)); return y;
}

__device__ __forceinline__ float softplus_ref(float x) {
    return fmaxf(x, 0.0f) + log1pf(expf(-fabsf(x)));
}
__device__ __forceinline__ float sigmoid_ref(float x) {
    if (x >= 0.0f) { float e = expf(-x); return 1.0f / (1.0f + e); }
    float e = expf(x); return e / (1.0f + e);
}

// ---- per-mode parameter computation ----------------------------------------
// A = {w1s (sign-folded), nsig = -sigK*log2e, lc = log2|coef|, A1}
// B = {A2, B2, B1, invB1}
__device__ void prep_mode(int i,
                          const float* mu_raw, const float* Dmu_raw,
                          const float* T0mu_raw, const float* Ly_raw,
                          const float* xo_raw, const float* yo_raw,
                          float4* outA, float4* outB)
{
    const float K_F   = (float)(1.0 / 44100.0);
    const float KK_F  = (float)((1.0 / 44100.0) * (1.0 / 44100.0));
    const float PI_F  = (float)M_PI;
    const float XIPI  = (float)((0.1 * 0.5) * M_PI);
    const float MAXOM = (float)(10000.0 * 2.0 * M_PI);
    const float MINOM = (float)(20.0 * 2.0 * M_PI);
    const double OM2SQ_D = (2.0 * M_PI * 500.0) * (2.0 * M_PI * 500.0);
    const float ALPHA_F = (float)(3.0 * log(10.0) / OM2SQ_D * (OM2SQ_D / 6.0));
    const float BETA_F  = (float)(3.0 * log(10.0) / OM2SQ_D * (1.0 / 1.0 - 1.0 / 6.0));

    float mu  = __fmul_rn(__fadd_rn(softplus_ref(*mu_raw),   1e-4f), 2.43f);
    float Dm  = __fmul_rn(__fadd_rn(softplus_ref(*Dmu_raw),  1e-4f), 0.002452f);
    float T0m = __fmul_rn(__fadd_rn(softplus_ref(*T0mu_raw), 1e-4f), 0.004115f);
    float Ly  = __fadd_rn(1.1f, __fmul_rn((float)(4.0 - 1.1), sigmoid_ref(*Ly_raw)));
    float xo  = __fadd_rn((float)(0.49 * 0.5),
                          __fmul_rn((float)((1.0 - 0.49) * 0.5), sigmoid_ref(*xo_raw)));
    float yo  = __fadd_rn(__fmul_rn(0.51f, Ly),
                          __fmul_rn(__fmul_rn((float)(1.0 - 0.51), Ly), sigmoid_ref(*yo_raw)));
    float yi  = __fmul_rn(0.1f, Ly);
    float ms  = __fmul_rn(__fmul_rn(__fmul_rn(0.25f, mu), 0.5f), Ly);

    float mf = (float)(i / MMAXI + 1);
    float nf = (float)(i % MMAXI + 1);
    float a = __fdiv_rn(__fmul_rn(mf, PI_F), 0.5f);
    float b = __fdiv_rn(__fmul_rn(nf, PI_F), Ly);
    float g1 = __fadd_rn(__fmul_rn(a, a), __fmul_rn(b, b));
    float osq = __fadd_rn(__fmul_rn(T0m, g1), __fmul_rn(__fmul_rn(Dm, g1), g1));
    float omega = sqrtf(fmaxf(osq, 0.0f));
    float valid = (omega <= MAXOM && omega >= MINOM) ? 1.0f : 0.0f;

    float InW = __fmul_rn(
        cosf(__fdiv_rn(__fmul_rn(XIPI, mf), 0.5f)),
        cosf(__fdiv_rn(__fmul_rn(__fmul_rn(yi, PI_F), nf), Ly)));
    float OutW = __fmul_rn(
        cosf(__fdiv_rn(__fmul_rn(__fmul_rn(xo, PI_F), mf), 0.5f)),
        cosf(__fdiv_rn(__fmul_rn(__fmul_rn(yo, PI_F), nf), Ly)));

    float sigma = __fadd_rn(ALPHA_F, __fmul_rn(BETA_F, __fmul_rn(omega, omega)));
    float e0 = expf(__fmul_rn(-sigma, K_F));
    float P = __fmul_rn(
        __fdiv_rn(__fmul_rn(__fmul_rn(__fmul_rn(OutW, InW), KK_F), e0), ms), valid);

    float w1   = __fmul_rn(omega, K_F);
    float s1   = sinf(w1);
    float c1   = cosf(w1);
    float c2w  = cosf(2.0f * w1);
    float den  = __fadd_rn(s1, 1e-8f);
    float coef = __fdiv_rn(P, den);
    float sigK = __fmul_rn(sigma, K_F);
    float e1   = expf(-sigK);
    float e2   = e1 * e1;

    // fold sign of coef into w1 (sin odd; A1,B1,A2,B2 even in omega)
    float w1s = (coef < 0.0f) ? -w1 : w1;
    float lc  = log2f(fabsf(coef));          // -inf when coef == 0 -> e = 0

    float A1 = 2.0f * e1 * c1;
    float B1 = -e2;
    float invB1 = -1.0f / e2;
    float A2 = 2.0f * e2 * c2w;
    float B2 = -(e2 * e2);

    *outA = make_float4(w1s, -sigK * 1.4426950408889634f, lc, A1);
    *outB = make_float4(A2, B2, B1, invB1);
}

// seed a mode: returns packed (Ucur, Uprev) for samples (t0, t0+1)/(t0-2, t0-1)
__device__ __forceinline__ void seed_mode(float4 A, float4 B,
                                          float t0f, float t0m1f, float t0m2f,
                                          u64t* Ucur, u64t* Uprev)
{
    const float TWOOPI = 0.63661977236758134f;
    const float TPI_HI = 6.283185482025146484375f;   // fl32(2*pi)
    const float TPI_LO = -1.7484555e-7f;             // 2*pi - TPI_HI

    float ph = t0f * A.x;
    float q  = rintf(ph * TWOOPI);
    float r  = fmaf(q, -TPI_HI, ph);
    r        = fmaf(q, -TPI_LO, r);
    float u0 = ex2a(fmaf(t0m1f, A.y, A.z)) * __sinf(r);

    float phm = t0m1f * A.x;
    float qm  = rintf(phm * TWOOPI);
    float rm  = fmaf(qm, -TPI_HI, phm);
    rm        = fmaf(qm, -TPI_LO, rm);
    float um1 = ex2a(fmaf(t0m2f, A.y, A.z)) * __sinf(rm);

    float u1  = fmaf(A.w, u0, B.z * um1);          // A1*u0 + B1*u(-1)
    float um2 = fmaf(-A.w, um1, u0) * B.w;         // (u0 - A1*u(-1)) * invB1

    *Ucur  = pack2(u0, u1);
    *Uprev = pack2(um2, um1);
}

// ---- the single persistent kernel ------------------------------------------
__global__ void __launch_bounds__(TPB, 10)
plate_kernel(const float* mu_raw, const float* Dmu_raw,
             const float* T0mu_raw, const float* Ly_raw,
             const float* xo_raw, const float* yo_raw,
             float* __restrict__ out, int T)
{
    __shared__ float4 smA[CHUNK];
    __shared__ float4 smB[CHUNK];

    // reset inter-launch state (no block reaches the barrier for many us)
    if (blockIdx.x == 0 && blockIdx.y == 0 && threadIdx.x == 0) {
        g_peak_bits = 0u;
        g_c1 = 0u;
        g_c2 = 0u;
        __threadfence();
    }

    int base = blockIdx.y * CHUNK;
    if (threadIdx.x < CHUNK) {
        prep_mode(base + threadIdx.x, mu_raw, Dmu_raw, T0mu_raw,
                  Ly_raw, xo_raw, yo_raw,
                  &smA[threadIdx.x], &smB[threadIdx.x]);
    }
    __syncthreads();

    // ---------------- phase 1: synthesis ----------------
    int g = blockIdx.x * TPB + threadIdx.x;      // 0..703, exact
    int   t0    = g * SPT;
    float t0f   = (float)t0;
    float t0m1f = t0f - 1.0f;
    float t0m2f = t0f - 2.0f;

    u64t acc[SPT / 2];
    #pragma unroll
    for (int k = 0; k < SPT / 2; ++k) acc[k] = 0ull;

    #pragma unroll 1
    for (int j = 0; j < CHUNK; j += 2) {
        float4 Aa = smA[j],     Ba = smB[j];
        float4 Ab = smA[j + 1], Bb = smB[j + 1];

        u64t Ua, Pa, Ub, Pb;
        seed_mode(Aa, Ba, t0f, t0m1f, t0m2f, &Ua, &Pa);
        seed_mode(Ab, Bb, t0f, t0m1f, t0m2f, &Ub, &Pb);

        u64t A2a = pack2(Ba.x, Ba.x), B2a = pack2(Ba.y, Ba.y);
        u64t A2b = pack2(Bb.x, Bb.x), B2b = pack2(Bb.y, Bb.y);

        acc[0] = add2(acc[0], add2(Ua, Ub));
        #pragma unroll
        for (int k = 1; k < SPT / 2; ++k) {
            u64t na = fma2(A2a, Ua, mul2(B2a, Pa));   // chain a
            u64t nb = fma2(A2b, Ub, mul2(B2b, Pb));   // chain b (independent)
            acc[k] = add2(acc[k], add2(na, nb));
            Pa = Ua; Ua = na;
            Pb = Ub; Ub = nb;
        }
    }

    {
        float4* dst = reinterpret_cast<float4*>(&g_part[blockIdx.y][t0]);
        #pragma unroll
        for (int k = 0; k < SPT / 2; k += 2) {
            float2 p  = unpack2(acc[k]);
            float2 qq = unpack2(acc[k + 1]);
            dst[k / 2] = make_float4(p.x, p.y, qq.x, qq.y);
        }
    }

    // ---------------- barrier 1 (all 1408 blocks resident) ----------------
    __threadfence();
    __syncthreads();
    if (threadIdx.x == 0) {
        atomicAdd(&g_c1, 1u);
        while (*((volatile unsigned*)&g_c1) < (unsigned)NBLK) __nanosleep(128);
    }
    __syncthreads();
    __threadfence();

    // ---------------- phase 2: combine + peak ----------------
    unsigned lin  = blockIdx.y * XBLK + blockIdx.x;          // 0..1407
    unsigned gtid = lin * TPB + threadIdx.x;                 // 0..90111
    int t   = (int)(gtid >> 2);                              // 0..22527
    int sub = (int)(gtid & 3u);

    float v = 0.0f;
    {
        const float* col = &g_part[sub * 32][t];
        #pragma unroll
        for (int c = 0; c < 32; ++c)
            v += col[(size_t)c * TROW];
    }
    v += __shfl_down_sync(0xffffffffu, v, 2, 4);
    v += __shfl_down_sync(0xffffffffu, v, 1, 4);

    float av = (sub == 0 && t < T) ? fabsf(v) : 0.0f;
    unsigned b = __reduce_max_sync(0xffffffffu, __float_as_uint(av));
    if ((threadIdx.x & 31) == 0) atomicMax(&g_peak_bits, b);

    // ---------------- barrier 2 ----------------
    __syncthreads();
    if (threadIdx.x == 0) {
        __threadfence();
        atomicAdd(&g_c2, 1u);
        while (*((volatile unsigned*)&g_c2) < (unsigned)NBLK) __nanosleep(64);
    }
    __syncthreads();

    float peak = __uint_as_float(*((volatile unsigned*)&g_peak_bits));
    if (sub == 0 && t < T)
        out[t] = __fdiv_rn(v, __fadd_rn(peak, 1e-8f));
}

// ---------------------------------------------------------------------------
extern "C" void kernel_launch(void* const* d_in, const int* in_sizes, int n_in,
                              void* d_out, int out_size)
{
    const float* mu_raw   = (const float*)d_in[0];
    const float* Dmu_raw  = (const float*)d_in[1];
    const float* T0mu_raw = (const float*)d_in[2];
    const float* Ly_raw   = (const float*)d_in[3];
    const float* xo_raw   = (const float*)d_in[4];
    const float* yo_raw   = (const float*)d_in[5];
    float* out = (float*)d_out;

    int T = out_size;
    if (T > TROW) T = TROW;

    dim3 grid(XBLK, NCHUNK);
    plate_kernel<<<grid, TPB>>>(mu_raw, Dmu_raw, T0mu_raw,
                                Ly_raw, xo_raw, yo_raw, out, T);
}

// round 10
// speedup vs baseline: 1.0949x; 1.0920x over previous
#include <cuda_runtime.h>
#include <math.h>

// ---------------------------------------------------------------------------
// DifferentiableModalPlate, round 9 — scalar-FFMA recurrence (no f32x2).
//   u_m(t) = coef_m * exp(-sigma_m (t-1) K) * sin(t * omega_m * K)
//   disp[t] = sum_m u_m(t);  out = disp / (max|disp| + 1e-8)
//
// Evidence R4-R7: every structural variant lands 43-48us; issue stuck ~28%
// regardless of ILP/occupancy -> packed fma.rn.f32x2 executes at ~1/4 the
// scalar FFMA pair rate on sm_103a. This round uses the scalar stride-1
// recurrence  u_{k+1} = A1*u_k + B1*u_{k-1}  (FMUL+FFMA+FADD per sample,
// chain latency = 1 FFMA), 2 modes in flight per thread, one sin/cos pair
// seeds both u(t0) and u(t0-1).
// Synth: 704 blocks x 64 thr (SPT=32, 64 chunks x 100 modes).
// Finish: 704 blocks x 128 thr, 4 threads/sample, software grid barrier.
// ---------------------------------------------------------------------------

#define TPB_S   64
#define SPT     32
#define CHUNK   100
#define NCHUNK  64           // CHUNK*NCHUNK == MODES
#define MODES   6400
#define MMAXI   80
#define TROW    22528        // 704*32
#define NGROUP  (TROW / SPT)             // 704
#define XBLK    (NGROUP / TPB_S)         // 11, exact
#define TPB_F   128
#define FBLK    (TROW * 4 / TPB_F)       // 704 blocks, 4 threads/sample

__device__ float    g_part[NCHUNK][TROW];   // 5.8 MB, L2-resident
__device__ unsigned g_peak_bits;
__device__ unsigned g_cnt;

__device__ __forceinline__ float ex2a(float x) {
    float y; asm("ex2.approx.f32 %0, %1;" : "=f"(y) : "f"(x)); return y;
}

__device__ __forceinline__ float softplus_ref(float x) {
    return fmaxf(x, 0.0f) + log1pf(expf(-fabsf(x)));
}
__device__ __forceinline__ float sigmoid_ref(float x) {
    if (x >= 0.0f) { float e = expf(-x); return 1.0f / (1.0f + e); }
    float e = expf(x); return e / (1.0f + e);
}

// ---- per-mode parameter computation ----------------------------------------
// A = {w1s (sign-folded), nsig = -sigK*log2e, lc = log2|coef|, A1}
// B = {B1, s1s = sgn*sin(w1), c1 = cos(w1), epK = e^{+sigK}}
__device__ void prep_mode(int i,
                          const float* mu_raw, const float* Dmu_raw,
                          const float* T0mu_raw, const float* Ly_raw,
                          const float* xo_raw, const float* yo_raw,
                          float4* outA, float4* outB)
{
    const float K_F   = (float)(1.0 / 44100.0);
    const float KK_F  = (float)((1.0 / 44100.0) * (1.0 / 44100.0));
    const float PI_F  = (float)M_PI;
    const float XIPI  = (float)((0.1 * 0.5) * M_PI);
    const float MAXOM = (float)(10000.0 * 2.0 * M_PI);
    const float MINOM = (float)(20.0 * 2.0 * M_PI);
    const double OM2SQ_D = (2.0 * M_PI * 500.0) * (2.0 * M_PI * 500.0);
    const float ALPHA_F = (float)(3.0 * log(10.0) / OM2SQ_D * (OM2SQ_D / 6.0));
    const float BETA_F  = (float)(3.0 * log(10.0) / OM2SQ_D * (1.0 / 1.0 - 1.0 / 6.0));

    float mu  = __fmul_rn(__fadd_rn(softplus_ref(*mu_raw),   1e-4f), 2.43f);
    float Dm  = __fmul_rn(__fadd_rn(softplus_ref(*Dmu_raw),  1e-4f), 0.002452f);
    float T0m = __fmul_rn(__fadd_rn(softplus_ref(*T0mu_raw), 1e-4f), 0.004115f);
    float Ly  = __fadd_rn(1.1f, __fmul_rn((float)(4.0 - 1.1), sigmoid_ref(*Ly_raw)));
    float xo  = __fadd_rn((float)(0.49 * 0.5),
                          __fmul_rn((float)((1.0 - 0.49) * 0.5), sigmoid_ref(*xo_raw)));
    float yo  = __fadd_rn(__fmul_rn(0.51f, Ly),
                          __fmul_rn(__fmul_rn((float)(1.0 - 0.51), Ly), sigmoid_ref(*yo_raw)));
    float yi  = __fmul_rn(0.1f, Ly);
    float ms  = __fmul_rn(__fmul_rn(__fmul_rn(0.25f, mu), 0.5f), Ly);

    float mf = (float)(i / MMAXI + 1);
    float nf = (float)(i % MMAXI + 1);
    float a = __fdiv_rn(__fmul_rn(mf, PI_F), 0.5f);
    float b = __fdiv_rn(__fmul_rn(nf, PI_F), Ly);
    float g1 = __fadd_rn(__fmul_rn(a, a), __fmul_rn(b, b));
    float osq = __fadd_rn(__fmul_rn(T0m, g1), __fmul_rn(__fmul_rn(Dm, g1), g1));
    float omega = sqrtf(fmaxf(osq, 0.0f));
    float valid = (omega <= MAXOM && omega >= MINOM) ? 1.0f : 0.0f;

    float InW = __fmul_rn(
        cosf(__fdiv_rn(__fmul_rn(XIPI, mf), 0.5f)),
        cosf(__fdiv_rn(__fmul_rn(__fmul_rn(yi, PI_F), nf), Ly)));
    float OutW = __fmul_rn(
        cosf(__fdiv_rn(__fmul_rn(__fmul_rn(xo, PI_F), mf), 0.5f)),
        cosf(__fdiv_rn(__fmul_rn(__fmul_rn(yo, PI_F), nf), Ly)));

    float sigma = __fadd_rn(ALPHA_F, __fmul_rn(BETA_F, __fmul_rn(omega, omega)));
    float e0 = expf(__fmul_rn(-sigma, K_F));
    float P = __fmul_rn(
        __fdiv_rn(__fmul_rn(__fmul_rn(__fmul_rn(OutW, InW), KK_F), e0), ms), valid);

    float w1   = __fmul_rn(omega, K_F);
    float s1   = sinf(w1);
    float c1   = cosf(w1);
    float den  = __fadd_rn(s1, 1e-8f);
    float coef = __fdiv_rn(P, den);
    float sigK = __fmul_rn(sigma, K_F);
    float e1   = expf(-sigK);

    // fold sign of coef into omega terms (sin odd; A1, B1, c1 even in omega)
    float sgn = (coef < 0.0f) ? -1.0f : 1.0f;
    float w1s = sgn * w1;
    float s1s = sgn * s1;
    float lc  = log2f(fabsf(coef));          // -inf when coef == 0 -> E = 0

    float A1 = 2.0f * e1 * c1;
    float B1 = -(e1 * e1);
    float epK = expf(sigK);

    *outA = make_float4(w1s, -sigK * 1.4426950408889634f, lc, A1);
    *outB = make_float4(B1, s1s, c1, epK);
}

// ---- synthesis kernel ------------------------------------------------------
__global__ void __launch_bounds__(TPB_S)
plate_synth_kernel(const float* mu_raw, const float* Dmu_raw,
                   const float* T0mu_raw, const float* Ly_raw,
                   const float* xo_raw, const float* yo_raw)
{
    const float TWOOPI = 0.63661977236758134f;
    const float TPI_HI = 6.283185482025146484375f;   // fl32(2*pi)
    const float TPI_LO = -1.7484555e-7f;             // 2*pi - TPI_HI

    __shared__ float4 smA[CHUNK];
    __shared__ float4 smB[CHUNK];

    if (blockIdx.x == 0 && blockIdx.y == 0 && threadIdx.x == 0) {
        g_peak_bits = 0u;        // reset inter-launch state for this replay
        g_cnt = 0u;
        __threadfence();
    }

    int base = blockIdx.y * CHUNK;
    for (int j = threadIdx.x; j < CHUNK; j += TPB_S) {
        prep_mode(base + j, mu_raw, Dmu_raw, T0mu_raw,
                  Ly_raw, xo_raw, yo_raw, &smA[j], &smB[j]);
    }
    __syncthreads();

    int g = blockIdx.x * TPB_S + threadIdx.x;    // 0..703, exact
    int   t0    = g * SPT;
    float t0f   = (float)t0;
    float t0m1f = t0f - 1.0f;

    float acc[SPT];
    #pragma unroll
    for (int k = 0; k < SPT; ++k) acc[k] = 0.0f;

    #pragma unroll 1
    for (int j = 0; j < CHUNK; j += 2) {
        float4 Aa = smA[j],     Ba = smB[j];
        float4 Ab = smA[j + 1], Bb = smB[j + 1];

        // ---- seed mode a: one range-reduction, sin+cos give u0 and u(-1)
        float pha = t0f * Aa.x;
        float qa  = rintf(pha * TWOOPI);
        float ra  = fmaf(qa, -TPI_HI, pha);
        ra        = fmaf(qa, -TPI_LO, ra);
        float s0a = __sinf(ra), c0a = __cosf(ra);
        float Ea  = ex2a(fmaf(t0m1f, Aa.y, Aa.z));   // |coef|*exp(-sig*(t0-1)K)
        float ua  = Ea * s0a;                        // u(t0)
        float upa = (Ea * Bb.w == Ea * Bb.w, Ea) * 0.0f; // placeholder (unused)
        upa = (Ea * Ba.w) * fmaf(s0a, Ba.z, -(c0a * Ba.y));  // u(t0-1)

        // ---- seed mode b
        float phb = t0f * Ab.x;
        float qb  = rintf(phb * TWOOPI);
        float rb  = fmaf(qb, -TPI_HI, phb);
        rb        = fmaf(qb, -TPI_LO, rb);
        float s0b = __sinf(rb), c0b = __cosf(rb);
        float Eb  = ex2a(fmaf(t0m1f, Ab.y, Ab.z));
        float ub  = Eb * s0b;
        float upb = (Eb * Bb.w) * fmaf(s0b, Bb.z, -(c0b * Bb.y));

        float A1a = Aa.w, B1a = Ba.x;
        float A1b = Ab.w, B1b = Bb.x;

        acc[0] += ua + ub;
        #pragma unroll
        for (int k = 1; k < SPT; ++k) {
            float pa = B1a * upa;                  // FMUL (independent of chain)
            float na = fmaf(A1a, ua, pa);          // FFMA (4-cyc chain)
            float pb = B1b * upb;
            float nb = fmaf(A1b, ub, pb);
            acc[k] += na + nb;
            upa = ua; ua = na;
            upb = ub; ub = nb;
        }
    }

    {
        float4* dst = reinterpret_cast<float4*>(&g_part[blockIdx.y][t0]);
        #pragma unroll
        for (int k = 0; k < SPT; k += 4)
            dst[k / 4] = make_float4(acc[k], acc[k + 1], acc[k + 2], acc[k + 3]);
    }
}

// ---- combine + peak + normalize (software grid barrier, 704 blocks) --------
__global__ void __launch_bounds__(TPB_F)
plate_finish_kernel(float* __restrict__ out, int T)
{
    unsigned gtid = blockIdx.x * TPB_F + threadIdx.x;   // 0..90111
    int t   = (int)(gtid >> 2);                         // 0..22527
    int sub = (int)(gtid & 3u);

    // fixed-order partial sum: rows [sub*16, sub*16+16)
    float v = 0.0f;
    {
        const float* col = &g_part[sub * 16][t];
        #pragma unroll
        for (int c = 0; c < 16; ++c)
            v += col[(size_t)c * TROW];
    }
    v += __shfl_down_sync(0xffffffffu, v, 2, 4);
    v += __shfl_down_sync(0xffffffffu, v, 1, 4);

    float av = (sub == 0 && t < T) ? fabsf(v) : 0.0f;
    unsigned b = __reduce_max_sync(0xffffffffu, __float_as_uint(av));
    if ((threadIdx.x & 31) == 0) atomicMax(&g_peak_bits, b);

    // grid-wide barrier (704 small blocks: all resident)
    __syncthreads();
    if (threadIdx.x == 0) {
        __threadfence();
        atomicAdd(&g_cnt, 1u);
        while (*((volatile unsigned*)&g_cnt) < (unsigned)FBLK) __nanosleep(64);
    }
    __syncthreads();

    float peak = __uint_as_float(*((volatile unsigned*)&g_peak_bits));
    if (sub == 0 && t < T)
        out[t] = __fdiv_rn(v, __fadd_rn(peak, 1e-8f));
}

// ---------------------------------------------------------------------------
extern "C" void kernel_launch(void* const* d_in, const int* in_sizes, int n_in,
                              void* d_out, int out_size)
{
    const float* mu_raw   = (const float*)d_in[0];
    const float* Dmu_raw  = (const float*)d_in[1];
    const float* T0mu_raw = (const float*)d_in[2];
    const float* Ly_raw   = (const float*)d_in[3];
    const float* xo_raw   = (const float*)d_in[4];
    const float* yo_raw   = (const float*)d_in[5];
    float* out = (float*)d_out;

    int T = out_size;
    if (T > TROW) T = TROW;

    dim3 grid(XBLK, NCHUNK);
    plate_synth_kernel<<<grid, TPB_S>>>(mu_raw, Dmu_raw, T0mu_raw,
                                        Ly_raw, xo_raw, yo_raw);
    plate_finish_kernel<<<FBLK, TPB_F>>>(out, T);
}